// round 2
// baseline (speedup 1.0000x reference)
#include <cuda_runtime.h>

// ============================================================================
// JointCrossAttention fused kernel set (fp32, FFMA2 SIMT) for sm_103a
//
// Stage A (enc_kernel):  enc1 = f1 @ enc1_w^T + b1 ; enc2 = f2 @ enc2_w^T + b2
// Stage B (mid_kernel):  aff_a = enc1 @ affa^T ; aff_v = enc2 @ affv^T
//                        pre_a = enc1 @ wa^T   ; pre_v = enc2 @ wv^T
// Stage C (fused_kernel): per (b, 64-row i-tile):
//   Ra[m,k]  = tanh(enc1[b,i]*aff_a[b,k]/16)
//   Ha       = relu(Ra @ wca^T + pre_a[i,:])
//   AE1      = Ha @ wha^T + enc1[i,:]
//   (same for v-side -> AE2)
//   h        = relu(AE1 @ fc1a^T + AE2 @ fc1b^T + fc1_b)
//   out[b,i] = h . fc2_w + fc2_b
// All intermediates live in SMEM; only weights stream from L2.
// ============================================================================

#define EDIM 256

__device__ float g_enc1[EDIM*EDIM];
__device__ float g_enc2[EDIM*EDIM];
__device__ float g_affa[EDIM*EDIM];
__device__ float g_affv[EDIM*EDIM];
__device__ float g_prea[EDIM*EDIM];
__device__ float g_prev[EDIM*EDIM];

typedef unsigned long long u64;

__device__ __forceinline__ u64 pack_dup(float x){
    u64 r; asm("mov.b64 %0, {%1, %2};" : "=l"(r) : "f"(x), "f"(x)); return r;
}
__device__ __forceinline__ void ffma2(u64 &d, u64 a, u64 b){
    asm("fma.rn.f32x2 %0, %1, %2, %0;" : "+l"(d) : "l"(a), "l"(b));
}
__device__ __forceinline__ float2 unpack2(u64 v){
    float lo, hi; asm("mov.b64 {%0, %1}, %2;" : "=f"(lo), "=f"(hi) : "l"(v));
    return make_float2(lo, hi);
}
__device__ __forceinline__ float tanh_fast(float x){
    // accurate for our tiny arguments (|x| << 1); tanh.approx.f32 is NOT
    // (its absolute error would be ~relative 1e-1 here).
    float e = __expf(2.0f * x);
    return __fdividef(e - 1.0f, e + 1.0f);
}

// ----------------------------------------------------------------------------
// Small generic NT-GEMM: C[256,256] = A[256,K] @ W[256,K]^T (+bias)
// 64x64 tile per CTA, 256 threads, 4x4 per thread. Perf non-critical (<0.5 GF).
// ----------------------------------------------------------------------------
__device__ __forceinline__ void gemm64_body(const float* __restrict__ A,
                                            const float* __restrict__ W,
                                            const float* __restrict__ bias,
                                            float* __restrict__ C, int K)
{
    __shared__ float As[64*32];
    __shared__ float Wk[32*64];
    int tid = threadIdx.x;
    int tc = tid & 15, tr = tid >> 4;
    int m0 = blockIdx.y * 64, n0 = blockIdx.x * 64;
    float acc[4][4] = {};

    for (int k0 = 0; k0 < K; k0 += 32){
        __syncthreads();
        #pragma unroll
        for (int r = 0; r < 2; r++){
            int lin = r*1024 + tid*4;
            int mm = lin >> 5, kk = lin & 31;
            float4 va = *(const float4*)&A[(m0+mm)*K + k0 + kk];
            *(float4*)&As[mm*32 + kk] = va;
            float4 vw = *(const float4*)&W[(n0+mm)*K + k0 + kk];
            Wk[(kk+0)*64 + mm] = vw.x;
            Wk[(kk+1)*64 + mm] = vw.y;
            Wk[(kk+2)*64 + mm] = vw.z;
            Wk[(kk+3)*64 + mm] = vw.w;
        }
        __syncthreads();
        #pragma unroll 8
        for (int kk = 0; kk < 32; kk++){
            float a[4], bf[4];
            #pragma unroll
            for (int i = 0; i < 4; i++) a[i] = As[(tr*4+i)*32 + kk];
            #pragma unroll
            for (int j = 0; j < 4; j++) bf[j] = Wk[kk*64 + tc + 16*j];
            #pragma unroll
            for (int i = 0; i < 4; i++)
                #pragma unroll
                for (int j = 0; j < 4; j++)
                    acc[i][j] += a[i] * bf[j];
        }
    }
    #pragma unroll
    for (int i = 0; i < 4; i++){
        int m = m0 + tr*4 + i;
        #pragma unroll
        for (int j = 0; j < 4; j++){
            int n = n0 + tc + 16*j;
            float v = acc[i][j];
            if (bias) v += bias[n];
            C[m*EDIM + n] = v;
        }
    }
}

__global__ void __launch_bounds__(256) enc_kernel(
    const float* __restrict__ f1, const float* __restrict__ f2,
    const float* __restrict__ w1, const float* __restrict__ b1,
    const float* __restrict__ w2, const float* __restrict__ b2)
{
    if (blockIdx.z == 0) gemm64_body(f1, w1, b1, g_enc1, 768);
    else                 gemm64_body(f2, w2, b2, g_enc2, 768);
}

__global__ void __launch_bounds__(256) mid_kernel(
    const float* __restrict__ affa, const float* __restrict__ affv,
    const float* __restrict__ wa,   const float* __restrict__ wv)
{
    switch (blockIdx.z){
        case 0: gemm64_body(g_enc1, affa, nullptr, g_affa, 256); break;
        case 1: gemm64_body(g_enc2, affv, nullptr, g_affv, 256); break;
        case 2: gemm64_body(g_enc1, wa,   nullptr, g_prea, 256); break;
        default:gemm64_body(g_enc2, wv,   nullptr, g_prev, 256); break;
    }
}

// ----------------------------------------------------------------------------
// Fused chain kernel.
// CTA = (b, 64-row i-tile). 256 threads: tr = warp (8), tc = lane (32).
// Thread output tile: 8 rows (m = tr*8+mi) x 8 cols as 4 n-pairs
// (n = 2*tc + 64*ni + {0,1}), accumulated in u64 f32x2 registers.
//
// Weight tile staging: Wt[kk][col] k-major with XOR swizzle
//   col = n ^ ((kk>>2)<<2)
// -> transpose-STS during load AND pairwise LDS.64 during compute are both
//    fully bank-conflict-free (verified: 32 distinct banks per phase).
// ----------------------------------------------------------------------------
#define MT 64
#define SM_S0 0
#define SM_S1 16384
#define SM_WT 32768
#define SM_AROW 40960
#define SM_VROW 41216
#define SM_E1 41472
#define SM_E2 41536
#define SMEM_FLOATS 41600
#define SMEM_BYTES (SMEM_FLOATS * 4)

__device__ __forceinline__ void zero_acc(u64 acc[8][4]){
    #pragma unroll
    for (int i = 0; i < 8; i++)
        #pragma unroll
        for (int j = 0; j < 4; j++) acc[i][j] = 0ull;
}

// One full K=256 pass: acc += Sin[64,256] @ Wg[:,kofs:kofs+256]^T
// Wg row-major [256, ldw]. Register-prefetched 32-wide K tiles.
__device__ __forceinline__ void gemm_pass(const float* __restrict__ Sin,
                                          float* __restrict__ Wt,
                                          const float* __restrict__ Wg,
                                          int ldw, int kofs,
                                          u64 acc[8][4])
{
    int tid = threadIdx.x;
    int tr = tid >> 5, tc = tid & 31;
    int kq = tid & 7;

    float4 v[8];
    #pragma unroll
    for (int r = 0; r < 8; r++){
        int n = (r*256 + tid) >> 3;
        v[r] = *(const float4*)&Wg[n*ldw + kofs + kq*4];
    }

    for (int kt = 0; kt < 8; kt++){
        __syncthreads();   // Wt free (previous compute done)
        #pragma unroll
        for (int r = 0; r < 8; r++){
            int n = (r*256 + tid) >> 3;
            int c = n ^ (kq << 2);           // XOR swizzle
            Wt[(kq*4+0)*256 + c] = v[r].x;
            Wt[(kq*4+1)*256 + c] = v[r].y;
            Wt[(kq*4+2)*256 + c] = v[r].z;
            Wt[(kq*4+3)*256 + c] = v[r].w;
        }
        __syncthreads();   // Wt ready
        if (kt < 7){
            #pragma unroll
            for (int r = 0; r < 8; r++){
                int n = (r*256 + tid) >> 3;
                v[r] = *(const float4*)&Wg[n*ldw + kofs + (kt+1)*32 + kq*4];
            }
        }
        const float* __restrict__ Sb = Sin + tr*8*256 + kt*32;
        #pragma unroll 4
        for (int kk = 0; kk < 32; kk++){
            const float* wr = Wt + kk*256;
            int s2 = kk & 28;                // (kk>>2)<<2, matches store swizzle
            u64 b0 = *(const u64*)(wr + ((2*tc      ) ^ s2));
            u64 b1 = *(const u64*)(wr + ((2*tc +  64) ^ s2));
            u64 b2 = *(const u64*)(wr + ((2*tc + 128) ^ s2));
            u64 b3 = *(const u64*)(wr + ((2*tc + 192) ^ s2));
            #pragma unroll
            for (int mi = 0; mi < 8; mi++){
                u64 a2 = pack_dup(Sb[mi*256 + kk]);
                ffma2(acc[mi][0], a2, b0);
                ffma2(acc[mi][1], a2, b1);
                ffma2(acc[mi][2], a2, b2);
                ffma2(acc[mi][3], a2, b3);
            }
        }
    }
}

// acc (+ addsrc[m,n]) (-> relu?) -> dst[m,n]   (addsrc pre-offset by i0*256)
__device__ __forceinline__ void epilogue_store(float* __restrict__ dst,
                                               const float* __restrict__ addsrc,
                                               u64 acc[8][4], bool do_relu,
                                               int tr, int tc)
{
    #pragma unroll
    for (int mi = 0; mi < 8; mi++){
        int m = tr*8 + mi;
        #pragma unroll
        for (int ni = 0; ni < 4; ni++){
            int n = 2*tc + 64*ni;
            float2 p = *(const float2*)&addsrc[m*256 + n];
            float2 x = unpack2(acc[mi][ni]);
            x.x += p.x; x.y += p.y;
            if (do_relu){ x.x = fmaxf(x.x, 0.f); x.y = fmaxf(x.y, 0.f); }
            *(float2*)&dst[m*256 + n] = x;
        }
    }
}

__global__ void __launch_bounds__(256, 1) fused_kernel(
    const float* __restrict__ wca, const float* __restrict__ wcv,
    const float* __restrict__ wha, const float* __restrict__ whv,
    const float* __restrict__ fc1, const float* __restrict__ fc1b,
    const float* __restrict__ fc2w, const float* __restrict__ fc2b,
    float* __restrict__ out)
{
    extern __shared__ float smem[];
    float* S0   = smem + SM_S0;
    float* S1   = smem + SM_S1;
    float* Wt   = smem + SM_WT;
    float* arow = smem + SM_AROW;
    float* vrow = smem + SM_VROW;
    float* e1   = smem + SM_E1;
    float* e2   = smem + SM_E2;

    int tid = threadIdx.x;
    int tr = tid >> 5, tc = tid & 31;
    int b  = blockIdx.y;
    int i0 = blockIdx.x * MT;

    arow[tid] = g_affa[b*256 + tid];
    vrow[tid] = g_affv[b*256 + tid];
    if (tid < 64){
        e1[tid] = g_enc1[b*256 + i0 + tid];
        e2[tid] = g_enc2[b*256 + i0 + tid];
    }
    __syncthreads();

    const float scale = 0.0625f;  // 1/sqrt(256)

    // Ra -> S0
    for (int idx = tid; idx < MT*256; idx += 256){
        int m = idx >> 8, k = idx & 255;
        S0[idx] = tanh_fast(e1[m] * arow[k] * scale);
    }
    // (gemm_pass's internal barriers cover the S0 fill)

    u64 acc[8][4];

    // Ha = relu(Ra @ wca^T + pre_a[i,:])  -> S1
    zero_acc(acc);
    gemm_pass(S0, Wt, wca, 256, 0, acc);
    epilogue_store(S1, g_prea + i0*256, acc, true, tr, tc);

    // AE1 = Ha @ wha^T + enc1[i,:]  -> S0  (S0/Ra dead; no one reads S0 now)
    zero_acc(acc);
    gemm_pass(S1, Wt, wha, 256, 0, acc);
    epilogue_store(S0, g_enc1 + i0*256, acc, false, tr, tc);

    // Rv -> S1 (must wait: all threads done reading S1 in the previous gemm)
    __syncthreads();
    for (int idx = tid; idx < MT*256; idx += 256){
        int m = idx >> 8, k = idx & 255;
        S1[idx] = tanh_fast(e2[m] * vrow[k] * scale);
    }

    // Hv = relu(Rv @ wcv^T + pre_v[i,:])  -> S1 in-place (sync before write)
    zero_acc(acc);
    gemm_pass(S1, Wt, wcv, 256, 0, acc);
    __syncthreads();
    epilogue_store(S1, g_prev + i0*256, acc, true, tr, tc);

    // AE2 = Hv @ whv^T + enc2[i,:]  -> S1 in-place
    zero_acc(acc);
    gemm_pass(S1, Wt, whv, 256, 0, acc);
    __syncthreads();
    epilogue_store(S1, g_enc2 + i0*256, acc, false, tr, tc);

    // h = relu(AE1 @ fc1[:, :256]^T + AE2 @ fc1[:, 256:]^T + fc1_b)
    zero_acc(acc);
    gemm_pass(S0, Wt, fc1, 512, 0,   acc);
    gemm_pass(S1, Wt, fc1, 512, 256, acc);

    // out[b, i] = h . fc2_w + fc2_b
    float psum[8] = {0,0,0,0,0,0,0,0};
    float2 bb[4], ww[4];
    #pragma unroll
    for (int ni = 0; ni < 4; ni++){
        int n = 2*tc + 64*ni;
        bb[ni] = *(const float2*)&fc1b[n];
        ww[ni] = *(const float2*)&fc2w[n];
    }
    #pragma unroll
    for (int mi = 0; mi < 8; mi++){
        #pragma unroll
        for (int ni = 0; ni < 4; ni++){
            float2 x = unpack2(acc[mi][ni]);
            float h0 = fmaxf(x.x + bb[ni].x, 0.f);
            float h1 = fmaxf(x.y + bb[ni].y, 0.f);
            psum[mi] += h0 * ww[ni].x + h1 * ww[ni].y;
        }
    }
    float c2 = *fc2b;
    #pragma unroll
    for (int mi = 0; mi < 8; mi++){
        float s = psum[mi];
        #pragma unroll
        for (int off = 16; off > 0; off >>= 1)
            s += __shfl_xor_sync(0xffffffffu, s, off);
        if (tc == 0)
            out[b*256 + i0 + tr*8 + mi] = s + c2;
    }
}

// ----------------------------------------------------------------------------
extern "C" void kernel_launch(void* const* d_in, const int* in_sizes, int n_in,
                              void* d_out, int out_size)
{
    const float* f1    = (const float*)d_in[0];
    const float* f2    = (const float*)d_in[1];
    const float* e1w   = (const float*)d_in[2];
    const float* e1b   = (const float*)d_in[3];
    const float* e2w   = (const float*)d_in[4];
    const float* e2b   = (const float*)d_in[5];
    const float* affa  = (const float*)d_in[6];
    const float* affv  = (const float*)d_in[7];
    const float* wa    = (const float*)d_in[8];
    const float* wv    = (const float*)d_in[9];
    const float* wca   = (const float*)d_in[10];
    const float* wcv   = (const float*)d_in[11];
    const float* wha   = (const float*)d_in[12];
    const float* whv   = (const float*)d_in[13];
    const float* fc1   = (const float*)d_in[14];
    const float* fc1b  = (const float*)d_in[15];
    const float* fc2w  = (const float*)d_in[16];
    const float* fc2b  = (const float*)d_in[17];
    float* out = (float*)d_out;

    enc_kernel<<<dim3(4,4,2), 256>>>(f1, f2, e1w, e1b, e2w, e2b);
    mid_kernel<<<dim3(4,4,4), 256>>>(affa, affv, wa, wv);

    cudaFuncSetAttribute(fused_kernel,
                         cudaFuncAttributeMaxDynamicSharedMemorySize, SMEM_BYTES);
    fused_kernel<<<dim3(4,256), 256, SMEM_BYTES>>>(
        wca, wcv, wha, whv, fc1, fc1b, fc2w, fc2b, out);
}

// round 5
// speedup vs baseline: 2.5222x; 2.5222x over previous
#include <cuda_runtime.h>
#include <cstdint>

// ============================================================================
// JointCrossAttention for sm_103a — dual-path:
//   * tcgen05 tf32 MMA path, compiled only when the arch-specific target
//     feature is available (sm_103a / sm_103f); harness's plain compute_103
//     PTX pass cannot assemble tcgen05, so it gets the fallback.
//   * SIMT FFMA2 fallback (= the proven round-2 kernel, retiled to the same
//     launch geometry: each CTA processes two 64-row halves).
// Both paths: grid (2,256), 256 threads, SMEM_BYTES dynamic smem.
// ============================================================================

#if defined(__CUDA_ARCH_FEAT_SM103_ALL) || \
    (defined(__CUDA_ARCH_FAMILY_SPECIFIC__) && __CUDA_ARCH_FAMILY_SPECIFIC__ >= 1000)
#define HAS_TC 1
#else
#define HAS_TC 0
#endif

#define EDIM 256

__device__ float g_enc1[EDIM*EDIM];
__device__ float g_enc2[EDIM*EDIM];
__device__ float g_affa[EDIM*EDIM];
__device__ float g_affv[EDIM*EDIM];
__device__ float g_prea[EDIM*EDIM];
__device__ float g_prev[EDIM*EDIM];

typedef unsigned int u32;
typedef unsigned long long u64;

// ---------------------------------------------------------------------------
// Shared helpers
// ---------------------------------------------------------------------------
__device__ __forceinline__ u64 pack_dup(float x){
    u64 r; asm("mov.b64 %0, {%1, %2};" : "=l"(r) : "f"(x), "f"(x)); return r;
}
__device__ __forceinline__ void ffma2(u64 &d, u64 a, u64 b){
    asm("fma.rn.f32x2 %0, %1, %2, %0;" : "+l"(d) : "l"(a), "l"(b));
}
__device__ __forceinline__ float2 unpack2(u64 v){
    float lo, hi; asm("mov.b64 {%0, %1}, %2;" : "=f"(lo), "=f"(hi) : "l"(v));
    return make_float2(lo, hi);
}
__device__ __forceinline__ float tanh_fast(float x){
    float e = __expf(2.0f * x);
    return __fdividef(e - 1.0f, e + 1.0f);
}

// ---------------------------------------------------------------------------
// Stage A/B: SIMT GEMM, 32x64 tile, 128 threads (target-independent)
// C[256,256] = A[256,K] @ W[256,K]^T (+bias)
// ---------------------------------------------------------------------------
__device__ __forceinline__ void sgemm_body(const float* __restrict__ A,
                                           const float* __restrict__ W,
                                           const float* __restrict__ bias,
                                           float* __restrict__ C, int K)
{
    __shared__ float As[32*32];
    __shared__ float Wk[32*64];
    int tid = threadIdx.x;
    int tc = tid & 15, tr = tid >> 4;
    int m0 = blockIdx.y * 32, n0 = blockIdx.x * 64;
    float acc[4][4] = {};

    for (int k0 = 0; k0 < K; k0 += 32){
        __syncthreads();
        #pragma unroll
        for (int r = 0; r < 2; r++){
            int lin = r*512 + tid*4;
            int mm = lin >> 5, kk = lin & 31;
            *(float4*)&As[mm*32 + kk] = *(const float4*)&A[(m0+mm)*K + k0 + kk];
        }
        #pragma unroll
        for (int r = 0; r < 4; r++){
            int lin = r*512 + tid*4;
            int nn = lin >> 5, kk = lin & 31;
            float4 vw = *(const float4*)&W[(n0+nn)*K + k0 + kk];
            Wk[(kk+0)*64 + nn] = vw.x;
            Wk[(kk+1)*64 + nn] = vw.y;
            Wk[(kk+2)*64 + nn] = vw.z;
            Wk[(kk+3)*64 + nn] = vw.w;
        }
        __syncthreads();
        #pragma unroll 8
        for (int kk = 0; kk < 32; kk++){
            float a[4], bf[4];
            #pragma unroll
            for (int i = 0; i < 4; i++) a[i] = As[(tr*4+i)*32 + kk];
            #pragma unroll
            for (int j = 0; j < 4; j++) bf[j] = Wk[kk*64 + tc + 16*j];
            #pragma unroll
            for (int i = 0; i < 4; i++)
                #pragma unroll
                for (int j = 0; j < 4; j++)
                    acc[i][j] += a[i] * bf[j];
        }
    }
    #pragma unroll
    for (int i = 0; i < 4; i++){
        int m = m0 + tr*4 + i;
        #pragma unroll
        for (int j = 0; j < 4; j++){
            int n = n0 + tc + 16*j;
            float v = acc[i][j];
            if (bias) v += bias[n];
            C[m*EDIM + n] = v;
        }
    }
}

__global__ void __launch_bounds__(128) enc_kernel(
    const float* __restrict__ f1, const float* __restrict__ f2,
    const float* __restrict__ w1, const float* __restrict__ b1,
    const float* __restrict__ w2, const float* __restrict__ b2)
{
    if (blockIdx.z == 0) sgemm_body(f1, w1, b1, g_enc1, 768);
    else                 sgemm_body(f2, w2, b2, g_enc2, 768);
}

__global__ void __launch_bounds__(128) mid_kernel(
    const float* __restrict__ affa, const float* __restrict__ affv,
    const float* __restrict__ wa,   const float* __restrict__ wv)
{
    switch (blockIdx.z){
        case 0: sgemm_body(g_enc1, affa, nullptr, g_affa, 256); break;
        case 1: sgemm_body(g_enc2, affv, nullptr, g_affv, 256); break;
        case 2: sgemm_body(g_enc1, wa,   nullptr, g_prea, 256); break;
        default:sgemm_body(g_enc2, wv,   nullptr, g_prev, 256); break;
    }
}

// ---------------------------------------------------------------------------
// SMEM map for the fused kernel (MMA layout; fallback reuses the same buffer)
// ---------------------------------------------------------------------------
#define SM_A     0          // 131072  A operand [128 x 256] tf32, SW128 atoms
#define SM_B0    131072     // 32768   B chunk buffer 0 [256 x 32] tf32
#define SM_B1    163840     // 32768   B chunk buffer 1
#define SM_AROW  196608     // 1024
#define SM_VROW  197632     // 1024
#define SM_E1    198656     // 512
#define SM_E2    199168     // 512
#define SM_FC1B  199680     // 1024
#define SM_FC2W  200704     // 1024
#define SM_MBAR  201728     // 16
#define SM_TPTR  201744     // 16
#define SMEM_BYTES 201760

#if HAS_TC
// ===========================================================================
// tcgen05 path
// ===========================================================================
__device__ __forceinline__ u32 elect_one_pred(){
    u32 p;
    asm volatile("{\n\t.reg .pred p;\n\telect.sync _|p, 0xFFFFFFFF;\n\t"
                 "selp.b32 %0, 1, 0, p;\n\t}" : "=r"(p));
    return p;
}
__device__ __forceinline__ u32 smem_u32(const void* p){
    u32 a;
    asm("{ .reg .u64 t; cvta.to.shared.u64 t, %1; cvt.u32.u64 %0, t; }"
        : "=r"(a) : "l"(p));
    return a;
}

#define MBARRIER_INIT(addr, cnt) \
    asm volatile("mbarrier.init.shared.b64 [%0], %1;" :: "r"(addr), "r"(cnt) : "memory")

#define MBARRIER_WAIT_PARITY(addr, par) do {                                   \
    u32 _m = (addr); u32 _p = (par); u32 _d;                                   \
    asm volatile("{\n\t.reg .pred p;\n\t"                                      \
        "mbarrier.try_wait.parity.acquire.cta.shared::cta.b64 p, [%1], %2;\n\t"\
        "selp.b32 %0, 1, 0, p;\n\t}" : "=r"(_d) : "r"(_m), "r"(_p) : "memory");\
    if (!_d) {                                                                 \
        asm volatile("{\n\t.reg .pred P1;\n\t"                                 \
        "WL_%=: mbarrier.try_wait.parity.acquire.cta.shared::cta.b64 P1, [%0], %1, 0x989680;\n\t" \
        "@P1 bra.uni WD_%=;\n\t bra.uni WL_%=;\n\t WD_%=:\n\t}"                \
        :: "r"(_m), "r"(_p) : "memory");                                       \
    }                                                                          \
} while(0)

#define TCGEN05_ALLOC(sa, n) \
    asm volatile("tcgen05.alloc.cta_group::1.sync.aligned.shared::cta.b32 [%0], %1;" \
                 :: "r"((u32)(sa)), "r"((u32)(n)) : "memory")
#define TCGEN05_DEALLOC(t, n) \
    asm volatile("tcgen05.dealloc.cta_group::1.sync.aligned.b32 %0, %1;" :: "r"(t), "r"(n))
#define TCGEN05_COMMIT(mb) \
    asm volatile("tcgen05.commit.cta_group::1.mbarrier::arrive::one.shared::cluster.b64 [%0];" \
                 :: "r"((u32)(mb)) : "memory")
#define TCGEN05_WAIT_LD()    asm volatile("tcgen05.wait::ld.sync.aligned;" ::: "memory")
#define TCGEN05_FENCE_AFTER()  asm volatile("tcgen05.fence::after_thread_sync;" ::: "memory")
#define TCGEN05_FENCE_BEFORE() asm volatile("tcgen05.fence::before_thread_sync;" ::: "memory")
#define FENCE_ASYNC() asm volatile("fence.proxy.async.shared::cta;" ::: "memory")

#define TCGEN05_LD_X32(r, ta) \
    asm volatile("tcgen05.ld.sync.aligned.32x32b.x32.b32 " \
        "{%0, %1, %2, %3, %4, %5, %6, %7, %8, %9, %10, %11, %12, %13, %14, %15, " \
        "%16, %17, %18, %19, %20, %21, %22, %23, %24, %25, %26, %27, %28, %29, %30, %31}, [%32];" \
        : "=r"((r)[0]),  "=r"((r)[1]),  "=r"((r)[2]),  "=r"((r)[3]),  \
          "=r"((r)[4]),  "=r"((r)[5]),  "=r"((r)[6]),  "=r"((r)[7]),  \
          "=r"((r)[8]),  "=r"((r)[9]),  "=r"((r)[10]), "=r"((r)[11]), \
          "=r"((r)[12]), "=r"((r)[13]), "=r"((r)[14]), "=r"((r)[15]), \
          "=r"((r)[16]), "=r"((r)[17]), "=r"((r)[18]), "=r"((r)[19]), \
          "=r"((r)[20]), "=r"((r)[21]), "=r"((r)[22]), "=r"((r)[23]), \
          "=r"((r)[24]), "=r"((r)[25]), "=r"((r)[26]), "=r"((r)[27]), \
          "=r"((r)[28]), "=r"((r)[29]), "=r"((r)[30]), "=r"((r)[31]) \
        : "r"(ta))

static constexpr u64 DESC_BASE_SW128 =
    (u64(2) << 61) | (u64(1) << 46) | (u64(64) << 32) | (u64(1) << 16);
#define MAKE_DESC(a) (DESC_BASE_SW128 | ((u64)((a) >> 4) & 0x3FFF))

// idesc: c=F32, a=TF32, b=TF32, K-major both, N=256, M=128
#define IDESC_TF32 0x8400910u

__device__ __forceinline__ void mma_tf32_ss(u32 d, u64 ad, u64 bd, bool acc){
    u32 en = acc ? 1u : 0u, z = 0u;
    asm volatile("{\n\t.reg .pred p;\n\tsetp.ne.u32 p, %5, 0;\n\t"
        "tcgen05.mma.cta_group::1.kind::tf32 [%0], %1, %2, %3, {%4, %4, %4, %4}, p;\n\t}"
        :: "r"(d), "l"(ad), "l"(bd), "r"(IDESC_TF32), "r"(z), "r"(en) : "memory");
}

// A layout: SW128 atoms (8 rows x 128B), atom = m/8 + (k/32)*16
__device__ __forceinline__ u32 aoff(int m, int k){
    u32 b = (u32)(((m >> 3) + (k >> 5)*16)*1024 + (m & 7)*128 + (k & 31)*4);
    return b ^ ((b >> 3) & 0x70);
}
__device__ __forceinline__ u32 boff16(int n, int g){
    return (u32)((n >> 3)*1024 + (n & 7)*128 + ((g ^ (n & 7)) << 4));
}

__device__ __forceinline__ float tanh_poly(float x){
    float ax = fabsf(x);
    if (ax > 0.4f) return tanhf(x);
    float x2 = x*x;
    float p = fmaf(x2, -5.3968254e-2f, 1.3333334e-1f);
    p = fmaf(x2, p, -3.3333334e-1f);
    return x * fmaf(x2, p, 1.0f);
}

__device__ __forceinline__ void gen_tanh(char* smem, const float* e, const float* row){
    int tid = threadIdx.x;
    for (int q = tid; q < 128*64; q += 256){
        int m  = q >> 6;
        int k4 = (q & 63) << 2;
        float s = e[m] * 0.0625f;
        float4 a = *(const float4*)&row[k4];
        float4 t;
        t.x = tanh_poly(s * a.x);
        t.y = tanh_poly(s * a.y);
        t.z = tanh_poly(s * a.z);
        t.w = tanh_poly(s * a.w);
        *(float4*)(smem + SM_A + aoff(m, k4)) = t;
    }
}

__device__ __forceinline__ void gemm_mma(char* smem, u32 smem_base,
                                         const float* __restrict__ Wg, int ldw,
                                         int kofs, u32 tmem_d, bool accum,
                                         u32 cnt[2])
{
    int tid = threadIdx.x;
    const float* src = Wg + (size_t)tid*ldw + kofs;
    u64 adesc = MAKE_DESC(smem_base + SM_A);

    float4 v[8];
    #pragma unroll
    for (int g = 0; g < 8; g++) v[g] = *(const float4*)(src + g*4);

    for (int c = 0; c < 8; c++){
        int buf = c & 1;
        char* B = smem + (buf ? SM_B1 : SM_B0);
        if (cnt[buf] > 0)
            MBARRIER_WAIT_PARITY(smem_base + SM_MBAR + buf*8, (cnt[buf]-1) & 1);
        #pragma unroll
        for (int g = 0; g < 8; g++)
            *(float4*)(B + boff16(tid, g)) = v[g];
        if (c < 7){
            #pragma unroll
            for (int g = 0; g < 8; g++)
                v[g] = *(const float4*)(src + (c+1)*32 + g*4);
        }
        FENCE_ASYNC();
        __syncthreads();
        if (tid < 32 && elect_one_pred()){
            u64 ad = adesc + (u64)c*1024;
            u64 bd = MAKE_DESC(smem_base + (buf ? SM_B1 : SM_B0));
            #pragma unroll
            for (int s = 0; s < 4; s++){
                bool en = accum || c > 0 || s > 0;
                mma_tf32_ss(tmem_d, ad + s*2, bd + s*2, en);
            }
            TCGEN05_COMMIT(smem_base + SM_MBAR + buf*8);
        }
        cnt[buf]++;
    }
}

__device__ __forceinline__ void wait_mma(u32 smem_base, const u32 cnt[2]){
    MBARRIER_WAIT_PARITY(smem_base + SM_MBAR + 8, (cnt[1]-1) & 1);
    TCGEN05_FENCE_AFTER();
}

__device__ __forceinline__ void epi_to_A(char* smem, u32 tmem_d,
                                         const float* __restrict__ addend,
                                         int i0, bool relu)
{
    int tid = threadIdx.x;
    if (tid < 128){
        int w = tid >> 5, lid = tid & 31;
        int m = w*32 + lid;
        const float4* ap = (const float4*)(addend + (size_t)(i0+m)*256);
        #pragma unroll
        for (int s = 0; s < 8; s++){
            u32 r[32];
            TCGEN05_LD_X32(r, tmem_d + s*32);
            TCGEN05_WAIT_LD();
            #pragma unroll
            for (int q = 0; q < 8; q++){
                float4 a = ap[s*8 + q];
                float4 x;
                x.x = __uint_as_float(r[q*4+0]) + a.x;
                x.y = __uint_as_float(r[q*4+1]) + a.y;
                x.z = __uint_as_float(r[q*4+2]) + a.z;
                x.w = __uint_as_float(r[q*4+3]) + a.w;
                if (relu){
                    x.x = fmaxf(x.x, 0.f); x.y = fmaxf(x.y, 0.f);
                    x.z = fmaxf(x.z, 0.f); x.w = fmaxf(x.w, 0.f);
                }
                *(float4*)(smem + SM_A + aoff(m, s*32 + q*4)) = x;
            }
        }
        TCGEN05_FENCE_BEFORE();
    }
}
#endif  // HAS_TC

// ---------------------------------------------------------------------------
// Fallback machinery (round-2 proven SIMT FFMA2 pipeline, 64-row tiles)
// ---------------------------------------------------------------------------
#define FB_S0 0
#define FB_S1 16384
#define FB_WT 32768
#define FB_AROW 40960
#define FB_VROW 41216
#define FB_E1 41472
#define FB_E2 41536

__device__ __forceinline__ void fb_zero(u64 acc[8][4]){
    #pragma unroll
    for (int i = 0; i < 8; i++)
        #pragma unroll
        for (int j = 0; j < 4; j++) acc[i][j] = 0ull;
}

__device__ __forceinline__ void fb_gemm(const float* __restrict__ Sin,
                                        float* __restrict__ Wt,
                                        const float* __restrict__ Wg,
                                        int ldw, int kofs, u64 acc[8][4])
{
    int tid = threadIdx.x;
    int tr = tid >> 5, tc = tid & 31;
    int kq = tid & 7;

    float4 v[8];
    #pragma unroll
    for (int r = 0; r < 8; r++){
        int n = (r*256 + tid) >> 3;
        v[r] = *(const float4*)&Wg[n*ldw + kofs + kq*4];
    }
    for (int kt = 0; kt < 8; kt++){
        __syncthreads();
        #pragma unroll
        for (int r = 0; r < 8; r++){
            int n = (r*256 + tid) >> 3;
            int c = n ^ (kq << 2);
            Wt[(kq*4+0)*256 + c] = v[r].x;
            Wt[(kq*4+1)*256 + c] = v[r].y;
            Wt[(kq*4+2)*256 + c] = v[r].z;
            Wt[(kq*4+3)*256 + c] = v[r].w;
        }
        __syncthreads();
        if (kt < 7){
            #pragma unroll
            for (int r = 0; r < 8; r++){
                int n = (r*256 + tid) >> 3;
                v[r] = *(const float4*)&Wg[n*ldw + kofs + (kt+1)*32 + kq*4];
            }
        }
        const float* __restrict__ Sb = Sin + tr*8*256 + kt*32;
        #pragma unroll 4
        for (int kk = 0; kk < 32; kk++){
            const float* wr = Wt + kk*256;
            int s2 = kk & 28;
            u64 b0 = *(const u64*)(wr + ((2*tc      ) ^ s2));
            u64 b1 = *(const u64*)(wr + ((2*tc +  64) ^ s2));
            u64 b2 = *(const u64*)(wr + ((2*tc + 128) ^ s2));
            u64 b3 = *(const u64*)(wr + ((2*tc + 192) ^ s2));
            #pragma unroll
            for (int mi = 0; mi < 8; mi++){
                u64 a2 = pack_dup(Sb[mi*256 + kk]);
                ffma2(acc[mi][0], a2, b0);
                ffma2(acc[mi][1], a2, b1);
                ffma2(acc[mi][2], a2, b2);
                ffma2(acc[mi][3], a2, b3);
            }
        }
    }
}

__device__ __forceinline__ void fb_epi(float* __restrict__ dst,
                                       const float* __restrict__ addsrc,
                                       u64 acc[8][4], bool do_relu,
                                       int tr, int tc)
{
    #pragma unroll
    for (int mi = 0; mi < 8; mi++){
        int m = tr*8 + mi;
        #pragma unroll
        for (int ni = 0; ni < 4; ni++){
            int n = 2*tc + 64*ni;
            float2 p = *(const float2*)&addsrc[m*256 + n];
            float2 x = unpack2(acc[mi][ni]);
            x.x += p.x; x.y += p.y;
            if (do_relu){ x.x = fmaxf(x.x, 0.f); x.y = fmaxf(x.y, 0.f); }
            *(float2*)&dst[m*256 + n] = x;
        }
    }
}

// ---------------------------------------------------------------------------
// Fused kernel: grid (2, 256), 256 threads, SMEM_BYTES dynamic smem
// ---------------------------------------------------------------------------
__global__ void __launch_bounds__(256, 1) fused_kernel(
    const float* __restrict__ wca, const float* __restrict__ wcv,
    const float* __restrict__ wha, const float* __restrict__ whv,
    const float* __restrict__ fc1, const float* __restrict__ fc1b,
    const float* __restrict__ fc2w, const float* __restrict__ fc2b,
    float* __restrict__ out)
{
    extern __shared__ char smem[];
    int tid = threadIdx.x;
    int b  = blockIdx.y;
    int i0 = blockIdx.x * 128;

#if HAS_TC
    u32 smem_base = smem_u32(smem);
    if (tid < 32) TCGEN05_ALLOC(smem_base + SM_TPTR, 512);
    if (tid == 0){
        MBARRIER_INIT(smem_base + SM_MBAR,     1);
        MBARRIER_INIT(smem_base + SM_MBAR + 8, 1);
    }
    {
        float* arow = (float*)(smem + SM_AROW);
        float* vrow = (float*)(smem + SM_VROW);
        float* f1b  = (float*)(smem + SM_FC1B);
        float* f2w  = (float*)(smem + SM_FC2W);
        arow[tid] = g_affa[b*256 + tid];
        vrow[tid] = g_affv[b*256 + tid];
        f1b[tid]  = fc1b[tid];
        f2w[tid]  = fc2w[tid];
        if (tid < 128){
            ((float*)(smem + SM_E1))[tid] = g_enc1[b*256 + i0 + tid];
            ((float*)(smem + SM_E2))[tid] = g_enc2[b*256 + i0 + tid];
        }
    }
    __syncthreads();

    u32 tmem;
    asm volatile("ld.shared.b32 %0, [%1];" : "=r"(tmem) : "r"(smem_base + SM_TPTR));
    u32 D0 = tmem, D1 = tmem + 256;
    u32 cnt[2] = {0, 0};

    const float* e1   = (const float*)(smem + SM_E1);
    const float* e2   = (const float*)(smem + SM_E2);
    const float* arow = (const float*)(smem + SM_AROW);
    const float* vrow = (const float*)(smem + SM_VROW);

    gen_tanh(smem, e1, arow);
    gemm_mma(smem, smem_base, wca, 256, 0,   D0, false, cnt);
    wait_mma(smem_base, cnt);
    epi_to_A(smem, D0, g_prea, i0, true);
    gemm_mma(smem, smem_base, wha, 256, 0,   D0, false, cnt);
    wait_mma(smem_base, cnt);
    epi_to_A(smem, D0, g_enc1, i0, false);
    gemm_mma(smem, smem_base, fc1, 512, 0,   D1, false, cnt);
    wait_mma(smem_base, cnt);

    gen_tanh(smem, e2, vrow);
    gemm_mma(smem, smem_base, wcv, 256, 0,   D0, false, cnt);
    wait_mma(smem_base, cnt);
    epi_to_A(smem, D0, g_prev, i0, true);
    gemm_mma(smem, smem_base, whv, 256, 0,   D0, false, cnt);
    wait_mma(smem_base, cnt);
    epi_to_A(smem, D0, g_enc2, i0, false);
    gemm_mma(smem, smem_base, fc1, 512, 256, D1, true,  cnt);
    wait_mma(smem_base, cnt);

    if (tid < 128){
        int w = tid >> 5, lid = tid & 31;
        int m = w*32 + lid;
        const float* f1b = (const float*)(smem + SM_FC1B);
        const float* f2w = (const float*)(smem + SM_FC2W);
        float acc = 0.f;
        #pragma unroll
        for (int s = 0; s < 8; s++){
            u32 r[32];
            TCGEN05_LD_X32(r, D1 + s*32);
            TCGEN05_WAIT_LD();
            #pragma unroll
            for (int j = 0; j < 32; j++){
                float h = fmaxf(__uint_as_float(r[j]) + f1b[s*32 + j], 0.f);
                acc += h * f2w[s*32 + j];
            }
        }
        out[b*256 + i0 + m] = acc + fc2b[0];
    }

    __syncthreads();
    if (tid < 32) TCGEN05_DEALLOC(tmem, 512);

#else  // ---------------- SIMT fallback (round-2 pipeline, two halves) ------
    float* fsm  = (float*)smem;
    float* S0   = fsm + FB_S0;
    float* S1   = fsm + FB_S1;
    float* Wt   = fsm + FB_WT;
    float* arow = fsm + FB_AROW;
    float* vrow = fsm + FB_VROW;
    float* e1   = fsm + FB_E1;
    float* e2   = fsm + FB_E2;

    int tr = tid >> 5, tc = tid & 31;
    arow[tid] = g_affa[b*256 + tid];
    vrow[tid] = g_affv[b*256 + tid];

    const float scale = 0.0625f;

    for (int h = 0; h < 2; h++){
        int i0h = i0 + h*64;
        __syncthreads();
        if (tid < 64){
            e1[tid] = g_enc1[b*256 + i0h + tid];
            e2[tid] = g_enc2[b*256 + i0h + tid];
        }
        __syncthreads();

        for (int idx = tid; idx < 64*256; idx += 256){
            int m = idx >> 8, k = idx & 255;
            S0[idx] = tanh_fast(e1[m] * arow[k] * scale);
        }

        u64 acc[8][4];

        fb_zero(acc);
        fb_gemm(S0, Wt, wca, 256, 0, acc);
        fb_epi(S1, g_prea + i0h*256, acc, true, tr, tc);

        fb_zero(acc);
        fb_gemm(S1, Wt, wha, 256, 0, acc);
        fb_epi(S0, g_enc1 + i0h*256, acc, false, tr, tc);

        __syncthreads();
        for (int idx = tid; idx < 64*256; idx += 256){
            int m = idx >> 8, k = idx & 255;
            S1[idx] = tanh_fast(e2[m] * vrow[k] * scale);
        }

        fb_zero(acc);
        fb_gemm(S1, Wt, wcv, 256, 0, acc);
        __syncthreads();
        fb_epi(S1, g_prev + i0h*256, acc, true, tr, tc);

        fb_zero(acc);
        fb_gemm(S1, Wt, whv, 256, 0, acc);
        __syncthreads();
        fb_epi(S1, g_enc2 + i0h*256, acc, false, tr, tc);

        fb_zero(acc);
        fb_gemm(S0, Wt, fc1, 512, 0,   acc);
        fb_gemm(S1, Wt, fc1, 512, 256, acc);

        float psum[8] = {0,0,0,0,0,0,0,0};
        float2 bb[4], ww[4];
        #pragma unroll
        for (int ni = 0; ni < 4; ni++){
            int n = 2*tc + 64*ni;
            bb[ni] = *(const float2*)&fc1b[n];
            ww[ni] = *(const float2*)&fc2w[n];
        }
        #pragma unroll
        for (int mi = 0; mi < 8; mi++){
            #pragma unroll
            for (int ni = 0; ni < 4; ni++){
                float2 x = unpack2(acc[mi][ni]);
                float h0 = fmaxf(x.x + bb[ni].x, 0.f);
                float h1 = fmaxf(x.y + bb[ni].y, 0.f);
                psum[mi] += h0 * ww[ni].x + h1 * ww[ni].y;
            }
        }
        float c2 = *fc2b;
        #pragma unroll
        for (int mi = 0; mi < 8; mi++){
            float s = psum[mi];
            #pragma unroll
            for (int off = 16; off > 0; off >>= 1)
                s += __shfl_xor_sync(0xffffffffu, s, off);
            if (tc == 0)
                out[b*256 + i0h + tr*8 + mi] = s + c2;
        }
    }
#endif
}

// ----------------------------------------------------------------------------
extern "C" void kernel_launch(void* const* d_in, const int* in_sizes, int n_in,
                              void* d_out, int out_size)
{
    const float* f1    = (const float*)d_in[0];
    const float* f2    = (const float*)d_in[1];
    const float* e1w   = (const float*)d_in[2];
    const float* e1b   = (const float*)d_in[3];
    const float* e2w   = (const float*)d_in[4];
    const float* e2b   = (const float*)d_in[5];
    const float* affa  = (const float*)d_in[6];
    const float* affv  = (const float*)d_in[7];
    const float* wa    = (const float*)d_in[8];
    const float* wv    = (const float*)d_in[9];
    const float* wca   = (const float*)d_in[10];
    const float* wcv   = (const float*)d_in[11];
    const float* wha   = (const float*)d_in[12];
    const float* whv   = (const float*)d_in[13];
    const float* fc1   = (const float*)d_in[14];
    const float* fc1b  = (const float*)d_in[15];
    const float* fc2w  = (const float*)d_in[16];
    const float* fc2b  = (const float*)d_in[17];
    float* out = (float*)d_out;

    enc_kernel<<<dim3(4, 8, 2), 128>>>(f1, f2, e1w, e1b, e2w, e2b);
    mid_kernel<<<dim3(4, 8, 4), 128>>>(affa, affv, wa, wv);

    cudaFuncSetAttribute(fused_kernel,
                         cudaFuncAttributeMaxDynamicSharedMemorySize, SMEM_BYTES);
    fused_kernel<<<dim3(2, 256), 256, SMEM_BYTES>>>(
        wca, wcv, wha, whv, fc1, fc1b, fc2w, fc2b, out);
}

// round 6
// speedup vs baseline: 4.7814x; 1.8957x over previous
#include <cuda_runtime.h>
#include <cstdint>

// ============================================================================
// JointCrossAttention for sm_103a — R6
//  * prep_kernel: pre-swizzles all chain weights into a 1.5MB staged buffer
//    (48 x 32KB chunks, SW128 smem image, consumption order).
//  * fused kernel (tcgen05 tf32): cluster(2) pairs the two i-halves of a batch
//    row; weights stream via cp.async.bulk + multicast (one 32KB copy per
//    cluster per chunk), double-buffered, MMA-paced. Warp-specialized:
//    warp7 = producer, warp0-elect = MMA issue, warps0-3 = epilogues.
//  * SIMT FFMA2 fallback for the plain compute_103 pass (unchanged from R5).
// ============================================================================

#if defined(__CUDA_ARCH_FEAT_SM103_ALL) || \
    (defined(__CUDA_ARCH_FAMILY_SPECIFIC__) && __CUDA_ARCH_FAMILY_SPECIFIC__ >= 1000)
#define HAS_TC 1
#else
#define HAS_TC 0
#endif

#define EDIM 256

__device__ float g_enc1[EDIM*EDIM];
__device__ float g_enc2[EDIM*EDIM];
__device__ float g_affa[EDIM*EDIM];
__device__ float g_affv[EDIM*EDIM];
__device__ float g_prea[EDIM*EDIM];
__device__ float g_prev[EDIM*EDIM];
// 48 chunks x 32KB, order: wca(8) wha(8) fc1a(8) wcv(8) whv(8) fc1b(8)
__device__ float g_staged[48*8192];

typedef unsigned int u32;
typedef unsigned long long u64;

// ---------------------------------------------------------------------------
// Shared helpers
// ---------------------------------------------------------------------------
__device__ __forceinline__ u64 pack_dup(float x){
    u64 r; asm("mov.b64 %0, {%1, %2};" : "=l"(r) : "f"(x), "f"(x)); return r;
}
__device__ __forceinline__ void ffma2(u64 &d, u64 a, u64 b){
    asm("fma.rn.f32x2 %0, %1, %2, %0;" : "+l"(d) : "l"(a), "l"(b));
}
__device__ __forceinline__ float2 unpack2(u64 v){
    float lo, hi; asm("mov.b64 {%0, %1}, %2;" : "=f"(lo), "=f"(hi) : "l"(v));
    return make_float2(lo, hi);
}
__device__ __forceinline__ float tanh_fast(float x){
    float e = __expf(2.0f * x);
    return __fdividef(e - 1.0f, e + 1.0f);
}

// B chunk smem image: [256 rows x 128B], SW128 atoms of 8 rows
__device__ __forceinline__ u32 boff16(int n, int g){
    return (u32)((n >> 3)*1024 + (n & 7)*128 + ((g ^ (n & 7)) << 4));
}

// ---------------------------------------------------------------------------
// prep: stage W chunks into g_staged in smem image layout (contiguous 32KB)
// ---------------------------------------------------------------------------
__global__ void __launch_bounds__(256) prep_kernel(
    const float* __restrict__ wca, const float* __restrict__ wcv,
    const float* __restrict__ wha, const float* __restrict__ whv,
    const float* __restrict__ fc1)
{
    int chunk = blockIdx.x;           // 0..47
    int g = chunk >> 3, c = chunk & 7;
    const float* W; int ldw, kofs;
    switch (g){
        case 0: W = wca; ldw = 256; kofs = 0;   break;
        case 1: W = wha; ldw = 256; kofs = 0;   break;
        case 2: W = fc1; ldw = 512; kofs = 0;   break;
        case 3: W = wcv; ldw = 256; kofs = 0;   break;
        case 4: W = whv; ldw = 256; kofs = 0;   break;
        default:W = fc1; ldw = 512; kofs = 256; break;
    }
    float* dst = g_staged + chunk*8192;
    for (int idx = threadIdx.x; idx < 256*32; idx += 256){
        int n = idx >> 5, k = idx & 31;
        float v = W[n*ldw + kofs + c*32 + k];
        dst[(boff16(n, k >> 2) >> 2) + (k & 3)] = v;
    }
}

// ---------------------------------------------------------------------------
// Stage A/B: SIMT GEMM, 32x32 tile, 128 threads, register prefetch
// C[256,256] = A[256,K] @ W[256,K]^T (+bias)
// ---------------------------------------------------------------------------
__device__ __forceinline__ void sgemm32(const float* __restrict__ A,
                                        const float* __restrict__ W,
                                        const float* __restrict__ bias,
                                        float* __restrict__ C, int K)
{
    __shared__ float As[32*33];
    __shared__ float Ws[32*33];
    int tid = threadIdx.x;
    int tc = tid & 15, tr = tid >> 4;
    int m0 = blockIdx.y * 32, n0 = blockIdx.x * 32;
    int l0 = tid*4, l1 = tid*4 + 512;
    int r0 = l0 >> 5, k0i = l0 & 31;
    int r1 = l1 >> 5, k1i = l1 & 31;

    float4 pa0 = *(const float4*)&A[(m0+r0)*K + k0i];
    float4 pa1 = *(const float4*)&A[(m0+r1)*K + k1i];
    float4 pw0 = *(const float4*)&W[(n0+r0)*K + k0i];
    float4 pw1 = *(const float4*)&W[(n0+r1)*K + k1i];

    float acc[4][2] = {};
    for (int k0 = 0; k0 < K; k0 += 32){
        __syncthreads();
        As[r0*33+k0i+0]=pa0.x; As[r0*33+k0i+1]=pa0.y; As[r0*33+k0i+2]=pa0.z; As[r0*33+k0i+3]=pa0.w;
        As[r1*33+k1i+0]=pa1.x; As[r1*33+k1i+1]=pa1.y; As[r1*33+k1i+2]=pa1.z; As[r1*33+k1i+3]=pa1.w;
        Ws[r0*33+k0i+0]=pw0.x; Ws[r0*33+k0i+1]=pw0.y; Ws[r0*33+k0i+2]=pw0.z; Ws[r0*33+k0i+3]=pw0.w;
        Ws[r1*33+k1i+0]=pw1.x; Ws[r1*33+k1i+1]=pw1.y; Ws[r1*33+k1i+2]=pw1.z; Ws[r1*33+k1i+3]=pw1.w;
        __syncthreads();
        if (k0 + 32 < K){
            pa0 = *(const float4*)&A[(m0+r0)*K + k0+32 + k0i];
            pa1 = *(const float4*)&A[(m0+r1)*K + k0+32 + k1i];
            pw0 = *(const float4*)&W[(n0+r0)*K + k0+32 + k0i];
            pw1 = *(const float4*)&W[(n0+r1)*K + k0+32 + k1i];
        }
        #pragma unroll 8
        for (int kk = 0; kk < 32; kk++){
            float a[4], bf[2];
            #pragma unroll
            for (int i = 0; i < 4; i++) a[i] = As[(tr*4+i)*33 + kk];
            #pragma unroll
            for (int j = 0; j < 2; j++) bf[j] = Ws[(tc*2+j)*33 + kk];
            #pragma unroll
            for (int i = 0; i < 4; i++)
                #pragma unroll
                for (int j = 0; j < 2; j++)
                    acc[i][j] += a[i] * bf[j];
        }
    }
    #pragma unroll
    for (int i = 0; i < 4; i++){
        int m = m0 + tr*4 + i;
        #pragma unroll
        for (int j = 0; j < 2; j++){
            int n = n0 + tc*2 + j;
            float v = acc[i][j];
            if (bias) v += bias[n];
            C[m*EDIM + n] = v;
        }
    }
}

__global__ void __launch_bounds__(128) enc_kernel(
    const float* __restrict__ f1, const float* __restrict__ f2,
    const float* __restrict__ w1, const float* __restrict__ b1,
    const float* __restrict__ w2, const float* __restrict__ b2)
{
    if (blockIdx.z == 0) sgemm32(f1, w1, b1, g_enc1, 768);
    else                 sgemm32(f2, w2, b2, g_enc2, 768);
}

__global__ void __launch_bounds__(128) mid_kernel(
    const float* __restrict__ affa, const float* __restrict__ affv,
    const float* __restrict__ wa,   const float* __restrict__ wv)
{
    switch (blockIdx.z){
        case 0: sgemm32(g_enc1, affa, nullptr, g_affa, 256); break;
        case 1: sgemm32(g_enc2, affv, nullptr, g_affv, 256); break;
        case 2: sgemm32(g_enc1, wa,   nullptr, g_prea, 256); break;
        default:sgemm32(g_enc2, wv,   nullptr, g_prev, 256); break;
    }
}

// ---------------------------------------------------------------------------
// SMEM map for the fused kernel
// ---------------------------------------------------------------------------
#define SM_A     0          // 131072  A operand [128 x 256] tf32, SW128 atoms
#define SM_B0    131072     // 32768   B chunk buffer 0
#define SM_B1    163840     // 32768   B chunk buffer 1
#define SM_AROW  196608     // 1024
#define SM_VROW  197632     // 1024
#define SM_E1    198656     // 512
#define SM_E2    199168     // 512
#define SM_FC1B  199680     // 1024
#define SM_FC2W  200704     // 1024
#define SM_MBAR  201728     // 40: full0 full1 empty0 empty1 done
#define SM_TPTR  201768     // 8
#define SMEM_BYTES 201776

#define SM_FULL(b)  (SM_MBAR + (b)*8)
#define SM_EMPTY(b) (SM_MBAR + 16 + (b)*8)
#define SM_DONE     (SM_MBAR + 32)

#if HAS_TC
// ===========================================================================
// tcgen05 path
// ===========================================================================
__device__ __forceinline__ u32 elect_one_pred(){
    u32 p;
    asm volatile("{\n\t.reg .pred p;\n\telect.sync _|p, 0xFFFFFFFF;\n\t"
                 "selp.b32 %0, 1, 0, p;\n\t}" : "=r"(p));
    return p;
}
__device__ __forceinline__ u32 smem_u32(const void* p){
    u32 a;
    asm("{ .reg .u64 t; cvta.to.shared.u64 t, %1; cvt.u32.u64 %0, t; }"
        : "=r"(a) : "l"(p));
    return a;
}
__device__ __forceinline__ u32 cluster_rank(){
    u32 r; asm("mov.u32 %0, %%cluster_ctarank;" : "=r"(r)); return r;
}

#define MBARRIER_INIT(addr, cnt) \
    asm volatile("mbarrier.init.shared.b64 [%0], %1;" :: "r"(addr), "r"(cnt) : "memory")
#define MBARRIER_EXPECT_TX(addr, bytes) \
    asm volatile("mbarrier.arrive.expect_tx.shared.b64 _, [%0], %1;" \
                 :: "r"((u32)(addr)), "r"((u32)(bytes)) : "memory")

#define MBARRIER_WAIT_PARITY(addr, par) do {                                   \
    u32 _m = (addr); u32 _p = (par); u32 _d;                                   \
    asm volatile("{\n\t.reg .pred p;\n\t"                                      \
        "mbarrier.try_wait.parity.acquire.cta.shared::cta.b64 p, [%1], %2;\n\t"\
        "selp.b32 %0, 1, 0, p;\n\t}" : "=r"(_d) : "r"(_m), "r"(_p) : "memory");\
    if (!_d) {                                                                 \
        asm volatile("{\n\t.reg .pred P1;\n\t"                                 \
        "WL_%=: mbarrier.try_wait.parity.acquire.cta.shared::cta.b64 P1, [%0], %1, 0x989680;\n\t" \
        "@P1 bra.uni WD_%=;\n\t bra.uni WL_%=;\n\t WD_%=:\n\t}"                \
        :: "r"(_m), "r"(_p) : "memory");                                       \
    }                                                                          \
} while(0)

#define TCGEN05_ALLOC(sa, n) \
    asm volatile("tcgen05.alloc.cta_group::1.sync.aligned.shared::cta.b32 [%0], %1;" \
                 :: "r"((u32)(sa)), "r"((u32)(n)) : "memory")
#define TCGEN05_DEALLOC(t, n) \
    asm volatile("tcgen05.dealloc.cta_group::1.sync.aligned.b32 %0, %1;" :: "r"(t), "r"(n))
#define TCGEN05_COMMIT(mb) \
    asm volatile("tcgen05.commit.cta_group::1.mbarrier::arrive::one.shared::cluster.b64 [%0];" \
                 :: "r"((u32)(mb)) : "memory")
#define TCGEN05_COMMIT_MC(mb, mask) \
    asm volatile("tcgen05.commit.cta_group::1.mbarrier::arrive::one.shared::cluster.multicast::cluster.b64 [%0], %1;" \
                 :: "r"((u32)(mb)), "h"((unsigned short)(mask)) : "memory")
#define TCGEN05_WAIT_LD()    asm volatile("tcgen05.wait::ld.sync.aligned;" ::: "memory")
#define TCGEN05_FENCE_AFTER()  asm volatile("tcgen05.fence::after_thread_sync;" ::: "memory")
#define TCGEN05_FENCE_BEFORE() asm volatile("tcgen05.fence::before_thread_sync;" ::: "memory")
#define FENCE_ASYNC() asm volatile("fence.proxy.async.shared::cta;" ::: "memory")
#define BAR224() asm volatile("bar.sync 1, 224;" ::: "memory")
#define CLUSTER_SYNC() do { \
    asm volatile("barrier.cluster.arrive.aligned;" ::: "memory"); \
    asm volatile("barrier.cluster.wait.aligned;"   ::: "memory"); } while(0)

__device__ __forceinline__ void bulk_mcast(u32 dst, const float* src, u32 mbar){
    asm volatile(
      "cp.async.bulk.shared::cluster.global.mbarrier::complete_tx::bytes.multicast::cluster "
      "[%0], [%1], %2, [%3], %4;"
      :: "r"(dst), "l"(src), "r"(32768u), "r"(mbar), "h"((unsigned short)3)
      : "memory");
}

#define TCGEN05_LD_X32(r, ta) \
    asm volatile("tcgen05.ld.sync.aligned.32x32b.x32.b32 " \
        "{%0, %1, %2, %3, %4, %5, %6, %7, %8, %9, %10, %11, %12, %13, %14, %15, " \
        "%16, %17, %18, %19, %20, %21, %22, %23, %24, %25, %26, %27, %28, %29, %30, %31}, [%32];" \
        : "=r"((r)[0]),  "=r"((r)[1]),  "=r"((r)[2]),  "=r"((r)[3]),  \
          "=r"((r)[4]),  "=r"((r)[5]),  "=r"((r)[6]),  "=r"((r)[7]),  \
          "=r"((r)[8]),  "=r"((r)[9]),  "=r"((r)[10]), "=r"((r)[11]), \
          "=r"((r)[12]), "=r"((r)[13]), "=r"((r)[14]), "=r"((r)[15]), \
          "=r"((r)[16]), "=r"((r)[17]), "=r"((r)[18]), "=r"((r)[19]), \
          "=r"((r)[20]), "=r"((r)[21]), "=r"((r)[22]), "=r"((r)[23]), \
          "=r"((r)[24]), "=r"((r)[25]), "=r"((r)[26]), "=r"((r)[27]), \
          "=r"((r)[28]), "=r"((r)[29]), "=r"((r)[30]), "=r"((r)[31]) \
        : "r"(ta))

static constexpr u64 DESC_BASE_SW128 =
    (u64(2) << 61) | (u64(1) << 46) | (u64(64) << 32) | (u64(1) << 16);
#define MAKE_DESC(a) (DESC_BASE_SW128 | ((u64)((a) >> 4) & 0x3FFF))

// idesc: c=F32, a=TF32, b=TF32, K-major both, N=256, M=128
#define IDESC_TF32 0x8400910u

__device__ __forceinline__ void mma_tf32_ss(u32 d, u64 ad, u64 bd, bool acc){
    u32 en = acc ? 1u : 0u, z = 0u;
    asm volatile("{\n\t.reg .pred p;\n\tsetp.ne.u32 p, %5, 0;\n\t"
        "tcgen05.mma.cta_group::1.kind::tf32 [%0], %1, %2, %3, {%4, %4, %4, %4}, p;\n\t}"
        :: "r"(d), "l"(ad), "l"(bd), "r"(IDESC_TF32), "r"(z), "r"(en) : "memory");
}

// A layout: SW128 atoms (8 rows x 128B), atom = m/8 + (k/32)*16
__device__ __forceinline__ u32 aoff(int m, int k){
    u32 b = (u32)(((m >> 3) + (k >> 5)*16)*1024 + (m & 7)*128 + (k & 31)*4);
    return b ^ ((b >> 3) & 0x70);
}

__device__ __forceinline__ float tanh_poly(float x){
    float ax = fabsf(x);
    if (ax > 0.4f) return tanhf(x);
    float x2 = x*x;
    float p = fmaf(x2, -5.3968254e-2f, 1.3333334e-1f);
    p = fmaf(x2, p, -3.3333334e-1f);
    return x * fmaf(x2, p, 1.0f);
}

// warps 0-6 (224 threads)
__device__ __forceinline__ void gen_tanh(char* smem, const float* e, const float* row){
    int tid = threadIdx.x;
    for (int q = tid; q < 128*64; q += 224){
        int m  = q >> 6;
        int k4 = (q & 63) << 2;
        float s = e[m] * 0.0625f;
        float4 a = *(const float4*)&row[k4];
        float4 t;
        t.x = tanh_poly(s * a.x);
        t.y = tanh_poly(s * a.y);
        t.z = tanh_poly(s * a.z);
        t.w = tanh_poly(s * a.w);
        *(float4*)(smem + SM_A + aoff(m, k4)) = t;
    }
}

// warps 0-3 only (caller guards tid<128)
__device__ __forceinline__ void epi_to_A(char* smem, u32 tmem_d,
                                         const float* __restrict__ addend,
                                         int i0, bool relu)
{
    int tid = threadIdx.x;
    int w = tid >> 5, lid = tid & 31;
    int m = w*32 + lid;
    const float4* ap = (const float4*)(addend + (size_t)(i0+m)*256);
    #pragma unroll
    for (int s = 0; s < 8; s++){
        u32 r[32];
        TCGEN05_LD_X32(r, tmem_d + s*32);
        TCGEN05_WAIT_LD();
        #pragma unroll
        for (int q = 0; q < 8; q++){
            float4 a = ap[s*8 + q];
            float4 x;
            x.x = __uint_as_float(r[q*4+0]) + a.x;
            x.y = __uint_as_float(r[q*4+1]) + a.y;
            x.z = __uint_as_float(r[q*4+2]) + a.z;
            x.w = __uint_as_float(r[q*4+3]) + a.w;
            if (relu){
                x.x = fmaxf(x.x, 0.f); x.y = fmaxf(x.y, 0.f);
                x.z = fmaxf(x.z, 0.f); x.w = fmaxf(x.w, 0.f);
            }
            *(float4*)(smem + SM_A + aoff(m, s*32 + q*4)) = x;
        }
    }
    TCGEN05_FENCE_BEFORE();
}
#endif  // HAS_TC

// ---------------------------------------------------------------------------
// Fallback machinery (round-2 proven SIMT FFMA2 pipeline)
// ---------------------------------------------------------------------------
#define FB_S0 0
#define FB_S1 16384
#define FB_WT 32768
#define FB_AROW 40960
#define FB_VROW 41216
#define FB_E1 41472
#define FB_E2 41536

__device__ __forceinline__ void fb_zero(u64 acc[8][4]){
    #pragma unroll
    for (int i = 0; i < 8; i++)
        #pragma unroll
        for (int j = 0; j < 4; j++) acc[i][j] = 0ull;
}

__device__ __forceinline__ void fb_gemm(const float* __restrict__ Sin,
                                        float* __restrict__ Wt,
                                        const float* __restrict__ Wg,
                                        int ldw, int kofs, u64 acc[8][4])
{
    int tid = threadIdx.x;
    int tr = tid >> 5, tc = tid & 31;
    int kq = tid & 7;

    float4 v[8];
    #pragma unroll
    for (int r = 0; r < 8; r++){
        int n = (r*256 + tid) >> 3;
        v[r] = *(const float4*)&Wg[n*ldw + kofs + kq*4];
    }
    for (int kt = 0; kt < 8; kt++){
        __syncthreads();
        #pragma unroll
        for (int r = 0; r < 8; r++){
            int n = (r*256 + tid) >> 3;
            int c = n ^ (kq << 2);
            Wt[(kq*4+0)*256 + c] = v[r].x;
            Wt[(kq*4+1)*256 + c] = v[r].y;
            Wt[(kq*4+2)*256 + c] = v[r].z;
            Wt[(kq*4+3)*256 + c] = v[r].w;
        }
        __syncthreads();
        if (kt < 7){
            #pragma unroll
            for (int r = 0; r < 8; r++){
                int n = (r*256 + tid) >> 3;
                v[r] = *(const float4*)&Wg[n*ldw + kofs + (kt+1)*32 + kq*4];
            }
        }
        const float* __restrict__ Sb = Sin + tr*8*256 + kt*32;
        #pragma unroll 4
        for (int kk = 0; kk < 32; kk++){
            const float* wr = Wt + kk*256;
            int s2 = kk & 28;
            u64 b0 = *(const u64*)(wr + ((2*tc      ) ^ s2));
            u64 b1 = *(const u64*)(wr + ((2*tc +  64) ^ s2));
            u64 b2 = *(const u64*)(wr + ((2*tc + 128) ^ s2));
            u64 b3 = *(const u64*)(wr + ((2*tc + 192) ^ s2));
            #pragma unroll
            for (int mi = 0; mi < 8; mi++){
                u64 a2 = pack_dup(Sb[mi*256 + kk]);
                ffma2(acc[mi][0], a2, b0);
                ffma2(acc[mi][1], a2, b1);
                ffma2(acc[mi][2], a2, b2);
                ffma2(acc[mi][3], a2, b3);
            }
        }
    }
}

__device__ __forceinline__ void fb_epi(float* __restrict__ dst,
                                       const float* __restrict__ addsrc,
                                       u64 acc[8][4], bool do_relu,
                                       int tr, int tc)
{
    #pragma unroll
    for (int mi = 0; mi < 8; mi++){
        int m = tr*8 + mi;
        #pragma unroll
        for (int ni = 0; ni < 4; ni++){
            int n = 2*tc + 64*ni;
            float2 p = *(const float2*)&addsrc[m*256 + n];
            float2 x = unpack2(acc[mi][ni]);
            x.x += p.x; x.y += p.y;
            if (do_relu){ x.x = fmaxf(x.x, 0.f); x.y = fmaxf(x.y, 0.f); }
            *(float2*)&dst[m*256 + n] = x;
        }
    }
}

// ---------------------------------------------------------------------------
// Fused kernel: grid (2, 256) as clusters of 2, 256 threads
// ---------------------------------------------------------------------------
__global__ void __launch_bounds__(256, 1) __cluster_dims__(2, 1, 1)
fused_kernel(
    const float* __restrict__ wca, const float* __restrict__ wcv,
    const float* __restrict__ wha, const float* __restrict__ whv,
    const float* __restrict__ fc1, const float* __restrict__ fc1b,
    const float* __restrict__ fc2w, const float* __restrict__ fc2b,
    float* __restrict__ out)
{
    extern __shared__ char smem[];
    int tid = threadIdx.x;
    int b  = blockIdx.y;
    int i0 = blockIdx.x * 128;

#if HAS_TC
    u32 smem_base = smem_u32(smem);
    int wid = tid >> 5;
    u32 rank = cluster_rank();

    if (wid == 0) TCGEN05_ALLOC(smem_base + SM_TPTR, 512);
    if (tid == 0){
        MBARRIER_INIT(smem_base + SM_FULL(0),  1);
        MBARRIER_INIT(smem_base + SM_FULL(1),  1);
        MBARRIER_INIT(smem_base + SM_EMPTY(0), 2);
        MBARRIER_INIT(smem_base + SM_EMPTY(1), 2);
        MBARRIER_INIT(smem_base + SM_DONE,     1);
    }
    {
        float* arow = (float*)(smem + SM_AROW);
        float* vrow = (float*)(smem + SM_VROW);
        float* f1b  = (float*)(smem + SM_FC1B);
        float* f2w  = (float*)(smem + SM_FC2W);
        arow[tid] = g_affa[b*256 + tid];
        vrow[tid] = g_affv[b*256 + tid];
        f1b[tid]  = fc1b[tid];
        f2w[tid]  = fc2w[tid];
        if (tid < 128){
            ((float*)(smem + SM_E1))[tid] = g_enc1[b*256 + i0 + tid];
            ((float*)(smem + SM_E2))[tid] = g_enc2[b*256 + i0 + tid];
        }
    }
    __syncthreads();
    CLUSTER_SYNC();

    u32 tmem;
    asm volatile("ld.shared.b32 %0, [%1];" : "=r"(tmem) : "r"(smem_base + SM_TPTR));
    u32 D0 = tmem, D1 = tmem + 256;

    if (wid == 7){
        // ---------------- producer warp ----------------
        if (elect_one_pred()){
            for (int c = 0; c < 50; c++){
                int buf = c & 1;
                if (c >= 2)
                    MBARRIER_WAIT_PARITY(smem_base + SM_EMPTY(buf), ((c>>1)-1)&1);
                if (c < 48){
                    MBARRIER_EXPECT_TX(smem_base + SM_FULL(buf), 32768);
                    if ((u32)(c & 1) == rank)
                        bulk_mcast(smem_base + SM_B0 + buf*32768,
                                   g_staged + c*8192,
                                   smem_base + SM_FULL(buf));
                }
            }
        }
        // fall through to final __syncthreads
    } else {
        // ---------------- consumer warps 0-6 ----------------
        const float* e1   = (const float*)(smem + SM_E1);
        const float* e2   = (const float*)(smem + SM_E2);
        const float* arow = (const float*)(smem + SM_AROW);
        const float* vrow = (const float*)(smem + SM_VROW);

        u64 adesc = MAKE_DESC(smem_base + SM_A);
        u64 bdesc0 = MAKE_DESC(smem_base + SM_B0);
        u64 bdesc1 = MAKE_DESC(smem_base + SM_B1);

        gen_tanh(smem, e1, arow);
        FENCE_ASYNC();
        BAR224();

        #pragma unroll 1
        for (int g = 0; g < 6; g++){
            u32 dsel = (g == 2 || g == 5) ? D1 : D0;
            bool accum = (g == 5);

            if (wid == 0){
                if (elect_one_pred()){
                    #pragma unroll 1
                    for (int j = 0; j < 8; j++){
                        int c = g*8 + j;
                        int buf = c & 1;
                        MBARRIER_WAIT_PARITY(smem_base + SM_FULL(buf), (c>>1)&1);
                        u64 ad = adesc + (u64)j*1024;
                        u64 bd = buf ? bdesc1 : bdesc0;
                        #pragma unroll
                        for (int s = 0; s < 4; s++){
                            bool en = accum || j > 0 || s > 0;
                            mma_tf32_ss(dsel, ad + s*2, bd + s*2, en);
                        }
                        TCGEN05_COMMIT_MC(smem_base + SM_EMPTY(buf), 3);
                    }
                    TCGEN05_COMMIT(smem_base + SM_DONE);
                }
            }

            if (g == 0 || g == 1 || g == 3 || g == 4){
                if (tid < 128){
                    MBARRIER_WAIT_PARITY(smem_base + SM_DONE, g & 1);
                    TCGEN05_FENCE_AFTER();
                    const float* add =
                        (g == 0) ? g_prea : (g == 1) ? g_enc1 :
                        (g == 3) ? g_prev : g_enc2;
                    bool relu = (g == 0 || g == 3);
                    epi_to_A(smem, D0, add, i0, relu);
                    FENCE_ASYNC();
                }
                BAR224();
            } else if (g == 2){
                MBARRIER_WAIT_PARITY(smem_base + SM_DONE, 0);
                TCGEN05_FENCE_AFTER();
                gen_tanh(smem, e2, vrow);
                FENCE_ASYNC();
                BAR224();
            } else {  // g == 5: final output epilogue
                if (tid < 128){
                    MBARRIER_WAIT_PARITY(smem_base + SM_DONE, 1);
                    TCGEN05_FENCE_AFTER();
                    int w = tid >> 5, lid = tid & 31;
                    int m = w*32 + lid;
                    const float* f1b = (const float*)(smem + SM_FC1B);
                    const float* f2w = (const float*)(smem + SM_FC2W);
                    float acc = 0.f;
                    #pragma unroll
                    for (int s = 0; s < 8; s++){
                        u32 r[32];
                        TCGEN05_LD_X32(r, D1 + s*32);
                        TCGEN05_WAIT_LD();
                        #pragma unroll
                        for (int jj = 0; jj < 32; jj++){
                            float h = fmaxf(__uint_as_float(r[jj]) + f1b[s*32 + jj], 0.f);
                            acc += h * f2w[s*32 + jj];
                        }
                    }
                    out[b*256 + i0 + m] = acc + fc2b[0];
                }
            }
        }
    }

    __syncthreads();
    if (wid == 0) TCGEN05_DEALLOC(tmem, 512);
    CLUSTER_SYNC();

#else  // ---------------- SIMT fallback (round-2 pipeline, two halves) ------
    float* fsm  = (float*)smem;
    float* S0   = fsm + FB_S0;
    float* S1   = fsm + FB_S1;
    float* Wt   = fsm + FB_WT;
    float* arow = fsm + FB_AROW;
    float* vrow = fsm + FB_VROW;
    float* e1   = fsm + FB_E1;
    float* e2   = fsm + FB_E2;

    int tr = tid >> 5, tc = tid & 31;
    arow[tid] = g_affa[b*256 + tid];
    vrow[tid] = g_affv[b*256 + tid];

    const float scale = 0.0625f;

    for (int h = 0; h < 2; h++){
        int i0h = i0 + h*64;
        __syncthreads();
        if (tid < 64){
            e1[tid] = g_enc1[b*256 + i0h + tid];
            e2[tid] = g_enc2[b*256 + i0h + tid];
        }
        __syncthreads();

        for (int idx = tid; idx < 64*256; idx += 256){
            int m = idx >> 8, k = idx & 255;
            S0[idx] = tanh_fast(e1[m] * arow[k] * scale);
        }

        u64 acc[8][4];

        fb_zero(acc);
        fb_gemm(S0, Wt, wca, 256, 0, acc);
        fb_epi(S1, g_prea + i0h*256, acc, true, tr, tc);

        fb_zero(acc);
        fb_gemm(S1, Wt, wha, 256, 0, acc);
        fb_epi(S0, g_enc1 + i0h*256, acc, false, tr, tc);

        __syncthreads();
        for (int idx = tid; idx < 64*256; idx += 256){
            int m = idx >> 8, k = idx & 255;
            S1[idx] = tanh_fast(e2[m] * vrow[k] * scale);
        }

        fb_zero(acc);
        fb_gemm(S1, Wt, wcv, 256, 0, acc);
        __syncthreads();
        fb_epi(S1, g_prev + i0h*256, acc, true, tr, tc);

        fb_zero(acc);
        fb_gemm(S1, Wt, whv, 256, 0, acc);
        __syncthreads();
        fb_epi(S1, g_enc2 + i0h*256, acc, false, tr, tc);

        fb_zero(acc);
        fb_gemm(S0, Wt, fc1, 512, 0,   acc);
        fb_gemm(S1, Wt, fc1, 512, 256, acc);

        float psum[8] = {0,0,0,0,0,0,0,0};
        float2 bb[4], ww[4];
        #pragma unroll
        for (int ni = 0; ni < 4; ni++){
            int n = 2*tc + 64*ni;
            bb[ni] = *(const float2*)&fc1b[n];
            ww[ni] = *(const float2*)&fc2w[n];
        }
        #pragma unroll
        for (int mi = 0; mi < 8; mi++){
            #pragma unroll
            for (int ni = 0; ni < 4; ni++){
                float2 x = unpack2(acc[mi][ni]);
                float h0 = fmaxf(x.x + bb[ni].x, 0.f);
                float h1 = fmaxf(x.y + bb[ni].y, 0.f);
                psum[mi] += h0 * ww[ni].x + h1 * ww[ni].y;
            }
        }
        float c2 = *fc2b;
        #pragma unroll
        for (int mi = 0; mi < 8; mi++){
            float s = psum[mi];
            #pragma unroll
            for (int off = 16; off > 0; off >>= 1)
                s += __shfl_xor_sync(0xffffffffu, s, off);
            if (tc == 0)
                out[b*256 + i0h + tr*8 + mi] = s + c2;
        }
    }
#endif
}

// ----------------------------------------------------------------------------
extern "C" void kernel_launch(void* const* d_in, const int* in_sizes, int n_in,
                              void* d_out, int out_size)
{
    const float* f1    = (const float*)d_in[0];
    const float* f2    = (const float*)d_in[1];
    const float* e1w   = (const float*)d_in[2];
    const float* e1b   = (const float*)d_in[3];
    const float* e2w   = (const float*)d_in[4];
    const float* e2b   = (const float*)d_in[5];
    const float* affa  = (const float*)d_in[6];
    const float* affv  = (const float*)d_in[7];
    const float* wa    = (const float*)d_in[8];
    const float* wv    = (const float*)d_in[9];
    const float* wca   = (const float*)d_in[10];
    const float* wcv   = (const float*)d_in[11];
    const float* wha   = (const float*)d_in[12];
    const float* whv   = (const float*)d_in[13];
    const float* fc1   = (const float*)d_in[14];
    const float* fc1b  = (const float*)d_in[15];
    const float* fc2w  = (const float*)d_in[16];
    const float* fc2b  = (const float*)d_in[17];
    float* out = (float*)d_out;

    prep_kernel<<<48, 256>>>(wca, wcv, wha, whv, fc1);
    enc_kernel<<<dim3(8, 8, 2), 128>>>(f1, f2, e1w, e1b, e2w, e2b);
    mid_kernel<<<dim3(8, 8, 4), 128>>>(affa, affv, wa, wv);

    cudaFuncSetAttribute(fused_kernel,
                         cudaFuncAttributeMaxDynamicSharedMemorySize, SMEM_BYTES);
    fused_kernel<<<dim3(2, 256), 256, SMEM_BYTES>>>(
        wca, wcv, wha, whv, fc1, fc1b, fc2w, fc2b, out);
}